// round 8
// baseline (speedup 1.0000x reference)
#include <cuda_runtime.h>
#include <cuda_bf16.h>

#define N_NODES 100000
#define N_EDGES 1000000
#define DF 64
#define NC 16
#define PRE_BLOCKS 98
#define PRE_THREADS 1024
#define PRE_TOTAL (PRE_BLOCKS * PRE_THREADS)   // 100352 >= N_NODES
#define GT_TILES ((N_NODES + 127) / 128)       // 782 gemm tiles

// ---------------- device scratch (no allocations allowed) ----------------
__device__ int      g_degi[N_NODES];
__device__ float    g_dinv[N_NODES];
__device__ int      g_off[N_NODES + 1];
__device__ int      g_cur[N_NODES];
__device__ int      g_bsum[PRE_BLOCKS];
__device__ int2     g_edge[N_EDGES];             // packed (src, bits(dinv[src]))
__device__ float    g_h1[(size_t)N_NODES * DF];  // X @ W1
__device__ float    g_h2[(size_t)N_NODES * NC];  // relu(agg1) @ W2
__device__ int      g_idx64;
__device__ unsigned g_barcnt[4];                 // cumulative grid-barrier tickets

// ---------------- cumulative grid barrier (graph-replay safe) -------------
__device__ __forceinline__ void grid_barrier(int i) {
    __syncthreads();
    if (threadIdx.x == 0) {
        __threadfence();
        unsigned tkt = atomicAdd(&g_barcnt[i], 1u) + 1u;
        unsigned target = ((tkt + (PRE_BLOCKS - 1u)) / PRE_BLOCKS) * PRE_BLOCKS;
        volatile unsigned* p = &g_barcnt[i];
        while (*p < target) { }
        __threadfence();
    }
    __syncthreads();
}

// ---------------- packed f32x2 helpers -------------------------------------
__device__ __forceinline__ unsigned long long fma_f32x2(unsigned long long a,
                                                        unsigned long long b,
                                                        unsigned long long c) {
    unsigned long long d;
    asm("fma.rn.f32x2 %0, %1, %2, %3;" : "=l"(d) : "l"(a), "l"(b), "l"(c));
    return d;
}
__device__ __forceinline__ unsigned long long dup_f32x2(float v) {
    unsigned long long d;
    asm("mov.b64 %0, {%1, %1};" : "=l"(d) : "f"(v));
    return d;
}

// ---------------- fused preprocessing + GEMM1 ------------------------------
__global__ __launch_bounds__(PRE_THREADS)
void prep_kernel(const void* __restrict__ edges,
                 const float* __restrict__ X,
                 const float* __restrict__ W1) {
    // 48KB smem buffer, phase-aliased
    __shared__ __align__(16) unsigned char smem_raw[49152];
    float  (*xs)[64]  = (float  (*)[64])smem_raw;            // 32768B (gemm)
    float2 (*wst)[32] = (float2 (*)[32])(smem_raw + 32768);  // 16384B (gemm)
    int* scan_sm = (int*)smem_raw;                           // scan phases

    int tid = blockIdx.x * PRE_THREADS + threadIdx.x;

    // Phase A: zero degrees + detect index width (block 0)
    if (tid < N_NODES) g_degi[tid] = 0;
    if (blockIdx.x == 0) {
        if (threadIdx.x == 0) scan_sm[0] = 0;
        __syncthreads();
        const int* e32 = (const int*)edges;
        int nz = 0;
        for (int j = threadIdx.x; j < 4096; j += PRE_THREADS)
            if (e32[2 * j + 1] != 0) nz = 1;
        if (nz) scan_sm[0] = 1;
        __syncthreads();
        if (threadIdx.x == 0) g_idx64 = (scan_sm[0] == 0) ? 1 : 0;
    }
    grid_barrier(0);

    int idx64 = g_idx64;
    const long long* e64 = (const long long*)edges;
    const int*       e32 = (const int*)edges;

    // Phase B: in-degree histogram + GEMM1 (h1 = X @ W1)
    for (int e = tid; e < N_EDGES; e += PRE_TOTAL) {
        int d = idx64 ? (int)e64[(long long)N_EDGES + e] : e32[N_EDGES + e];
        atomicAdd(&g_degi[d], 1);
    }
    {
        // stage W1 transposed as column pairs: wst[k][p] = (W1[k][2p], W1[k][2p+1])
        __syncthreads();
        for (int i = threadIdx.x; i < 64 * 32; i += PRE_THREADS) {
            int k = i >> 5, p = i & 31;
            wst[k][p] = ((const float2*)W1)[i];
        }
        int col_t  = threadIdx.x & 15;         // col pairs col_t, col_t+16
        int node_t = threadIdx.x >> 4;         // 0..63 -> 2 nodes each
        for (int tile = blockIdx.x; tile < GT_TILES; tile += PRE_BLOCKS) {
            int base = tile * 128;
            __syncthreads();
            for (int i = threadIdx.x; i < 128 * 64; i += PRE_THREADS) {
                int n = i >> 6, k = i & 63;
                int node = base + n;
                xs[n][k] = (node < N_NODES) ? X[(size_t)node * 64 + k] : 0.0f;
            }
            __syncthreads();
            unsigned long long acc[2][2] = {};
#pragma unroll 8
            for (int k = 0; k < 64; k++) {
                unsigned long long xv0 = dup_f32x2(xs[node_t * 2][k]);
                unsigned long long xv1 = dup_f32x2(xs[node_t * 2 + 1][k]);
                unsigned long long wv0 = *(const unsigned long long*)&wst[k][col_t];
                unsigned long long wv1 = *(const unsigned long long*)&wst[k][col_t + 16];
                acc[0][0] = fma_f32x2(xv0, wv0, acc[0][0]);
                acc[0][1] = fma_f32x2(xv0, wv1, acc[0][1]);
                acc[1][0] = fma_f32x2(xv1, wv0, acc[1][0]);
                acc[1][1] = fma_f32x2(xv1, wv1, acc[1][1]);
            }
#pragma unroll
            for (int i = 0; i < 2; i++) {
                int node = base + node_t * 2 + i;
                if (node < N_NODES) {
                    float2* out = (float2*)(g_h1 + (size_t)node * 64);
                    out[col_t]      = *(const float2*)&acc[i][0];
                    out[col_t + 16] = *(const float2*)&acc[i][1];
                }
            }
        }
    }
    grid_barrier(1);

    // Phase C: dinv + block-local inclusive scan
    int v = (tid < N_NODES) ? g_degi[tid] : 0;
    if (tid < N_NODES) g_dinv[tid] = rsqrtf((float)v + 1.0f);
    int lane = threadIdx.x & 31, w = threadIdx.x >> 5;
    int x = v;
#pragma unroll
    for (int off = 1; off < 32; off <<= 1) {
        int y = __shfl_up_sync(0xffffffffu, x, off);
        if (lane >= off) x += y;
    }
    if (lane == 31) scan_sm[w] = x;
    __syncthreads();
    if (w == 0) {
        int y = scan_sm[lane];
#pragma unroll
        for (int off = 1; off < 32; off <<= 1) {
            int z = __shfl_up_sync(0xffffffffu, y, off);
            if (lane >= off) y += z;
        }
        scan_sm[lane] = y;
    }
    __syncthreads();
    int incl_local = x + ((w > 0) ? scan_sm[w - 1] : 0);
    if (threadIdx.x == PRE_THREADS - 1) g_bsum[blockIdx.x] = incl_local;
    grid_barrier(2);

    // Phase D: cross-block prefix + write offsets/cursors
    if (threadIdx.x < 32) {
        int acc = 0;
        for (int j = threadIdx.x; j < blockIdx.x; j += 32) acc += g_bsum[j];
#pragma unroll
        for (int off = 16; off > 0; off >>= 1)
            acc += __shfl_xor_sync(0xffffffffu, acc, off);
        if (threadIdx.x == 0) scan_sm[32] = acc;
    }
    __syncthreads();
    int incl = incl_local + scan_sm[32];
    if (tid < N_NODES) {
        g_off[tid] = incl - v;
        g_cur[tid] = incl - v;
        if (tid == N_NODES - 1) g_off[N_NODES] = incl;
    }
    grid_barrier(3);

    // Phase E: counting-sort scatter into CSR (packed payload)
    for (int e = tid; e < N_EDGES; e += PRE_TOTAL) {
        int s, d;
        if (idx64) {
            s = (int)e64[e];
            d = (int)e64[(long long)N_EDGES + e];
        } else {
            s = e32[e];
            d = e32[N_EDGES + e];
        }
        int pos = atomicAdd(&g_cur[d], 1);
        g_edge[pos] = make_int2(s, __float_as_int(g_dinv[s]));
    }
}

// ------- agg1 + gemm2 fused (shuffle-broadcast edge batches) --------------
__global__ __launch_bounds__(256) void agg1_gemm2_kernel(const float* __restrict__ b1,
                                                         const float* __restrict__ W2) {
    __shared__ float w2s[64][17];    // [k][c], padded
    __shared__ float x1s[8][64];     // per-warp x1 row
    int tid = threadIdx.x;
    for (int i = tid; i < 64 * 16; i += 256) w2s[i >> 4][i & 15] = W2[i];
    __syncthreads();

    int wy = tid >> 5;               // warp id 0..7
    int lane = tid & 31;
    int node = blockIdx.x * 8 + wy;
    if (node >= N_NODES) return;

    const float2* h1 = (const float2*)g_h1;
    float di = g_dinv[node];
    float2 acc = h1[(size_t)node * 32 + lane];
    acc.x *= di; acc.y *= di;        // self loop (final *di below)
    int beg = g_off[node], end = g_off[node + 1];

    for (int bb = beg; bb < end; bb += 32) {
        int2 e = make_int2(0, 0);
        if (bb + lane < end) e = g_edge[bb + lane];
        int cnt = min(end - bb, 32);
#pragma unroll 4
        for (int j = 0; j < cnt; j++) {
            int   s = __shfl_sync(0xffffffffu, e.x, j);
            float w = __int_as_float(__shfl_sync(0xffffffffu, e.y, j));
            float2 v = __ldg(&h1[(size_t)s * 32 + lane]);
            acc.x = fmaf(v.x, w, acc.x);
            acc.y = fmaf(v.y, w, acc.y);
        }
    }

    float rx = fmaxf(fmaf(acc.x, di, b1[2 * lane]), 0.0f);
    float ry = fmaxf(fmaf(acc.y, di, b1[2 * lane + 1]), 0.0f);
    x1s[wy][2 * lane]     = rx;
    x1s[wy][2 * lane + 1] = ry;
    __syncwarp();

    // in-warp gemm2: h2[c] = sum_k x1[k] * W2[k][c]
    int c = lane & 15, h = lane >> 4;
    float s = 0.0f;
#pragma unroll
    for (int kk = 0; kk < 32; kk++) {
        int k = h * 32 + kk;
        s = fmaf(x1s[wy][k], w2s[k][c], s);
    }
    s += __shfl_xor_sync(0xffffffffu, s, 16);
    if (h == 0) g_h2[(size_t)node * 16 + c] = s;
}

// ------- agg2: out = A_hat h2 + b2 (2 nodes/warp, independent halves) -----
__global__ __launch_bounds__(256) void agg2_kernel(const float* __restrict__ b2,
                                                   float* __restrict__ dout) {
    int wy = threadIdx.x >> 5;
    int lane = threadIdx.x & 31;
    int half = lane >> 4;            // 0 or 1 -> own node
    int c = lane & 15;               // column within h2 row
    unsigned mask = half ? 0xFFFF0000u : 0x0000FFFFu;
    int node = blockIdx.x * 16 + wy * 2 + half;
    if (node >= N_NODES) return;

    float di = g_dinv[node];
    float acc = g_h2[(size_t)node * 16 + c] * di;
    int beg = g_off[node], end = g_off[node + 1];

    for (int bb = beg; bb < end; bb += 16) {
        int2 e = make_int2(0, 0);
        if (bb + c < end) e = g_edge[bb + c];
        int cnt = min(end - bb, 16);
        for (int j = 0; j < cnt; j++) {
            int   s = __shfl_sync(mask, e.x, (half << 4) + j);
            float w = __int_as_float(__shfl_sync(mask, e.y, (half << 4) + j));
            acc = fmaf(__ldg(&g_h2[(size_t)s * 16 + c]), w, acc);
        }
    }
    dout[(size_t)node * 16 + c] = fmaf(acc, di, b2[c]);
}

// ---------------- launch --------------------------------------------------
extern "C" void kernel_launch(void* const* d_in, const int* in_sizes, int n_in,
                              void* d_out, int out_size) {
    const float* X  = (const float*)d_in[0];
    const void*  EI = (const void*)d_in[1];
    const float* W1 = (const float*)d_in[2];
    const float* b1 = (const float*)d_in[3];
    const float* W2 = (const float*)d_in[4];
    const float* b2 = (const float*)d_in[5];
    float* dout = (float*)d_out;
    (void)in_sizes; (void)n_in; (void)out_size;

    prep_kernel<<<PRE_BLOCKS, PRE_THREADS>>>(EI, X, W1);
    agg1_gemm2_kernel<<<(N_NODES + 7) / 8, 256>>>(b1, W2);
    agg2_kernel<<<(N_NODES + 15) / 16, 256>>>(b2, dout);
}

// round 9
// speedup vs baseline: 1.1664x; 1.1664x over previous
#include <cuda_runtime.h>
#include <cuda_bf16.h>

#define N_NODES 100000
#define N_EDGES 1000000
#define DF 64
#define NC 16
#define SCAN_BLOCKS 148
#define SCAN_THREADS 1024
#define SCAN_TOTAL (SCAN_BLOCKS * SCAN_THREADS)   // 151552 >= N_NODES

// ---------------- device scratch (no allocations allowed) ----------------
__device__ int      g_degi[N_NODES];
__device__ float    g_dinv[N_NODES];
__device__ int      g_off[N_NODES + 1];
__device__ int      g_cur[N_NODES];
__device__ int      g_bsum[SCAN_BLOCKS];
__device__ int2     g_edge[N_EDGES];             // packed (src, bits(dinv[src]))
__device__ float    g_h1[(size_t)N_NODES * DF];  // X @ W1
__device__ float    g_h2[(size_t)N_NODES * NC];  // relu(agg1) @ W2
__device__ int      g_idx64;
__device__ unsigned g_barcnt[2];                 // cumulative grid-barrier tickets

// ---------------- cumulative grid barrier (graph-replay safe) -------------
__device__ __forceinline__ void grid_barrier(int i) {
    __syncthreads();
    if (threadIdx.x == 0) {
        __threadfence();
        unsigned tkt = atomicAdd(&g_barcnt[i], 1u) + 1u;
        unsigned target = ((tkt + (SCAN_BLOCKS - 1u)) / SCAN_BLOCKS) * SCAN_BLOCKS;
        volatile unsigned* p = &g_barcnt[i];
        while (*p < target) { }
        __threadfence();
    }
    __syncthreads();
}

// ---------------- packed f32x2 FMA ----------------------------------------
__device__ __forceinline__ unsigned long long fma_f32x2(unsigned long long a,
                                                        unsigned long long b,
                                                        unsigned long long c) {
    unsigned long long d;
    asm("fma.rn.f32x2 %0, %1, %2, %3;" : "=l"(d) : "l"(a), "l"(b), "l"(c));
    return d;
}

// ---------------- k1: zero degrees + detect index width --------------------
__global__ void zero_detect_kernel(const int* __restrict__ e32) {
    int i = blockIdx.x * blockDim.x + threadIdx.x;
    if (i < N_NODES) g_degi[i] = 0;
    if (blockIdx.x == 0) {
        __shared__ int any_nz;
        if (threadIdx.x == 0) any_nz = 0;
        __syncthreads();
        int nz = 0;
        for (int j = threadIdx.x; j < 4096; j += blockDim.x)
            if (e32[2 * j + 1] != 0) nz = 1;
        if (nz) any_nz = 1;
        __syncthreads();
        if (threadIdx.x == 0) g_idx64 = (any_nz == 0) ? 1 : 0;
    }
}

// ---------------- k2: in-degree histogram (full grid) ----------------------
__global__ void degree_kernel(const void* __restrict__ edges) {
    int e = blockIdx.x * blockDim.x + threadIdx.x;
    if (e >= N_EDGES) return;
    int d = g_idx64 ? (int)((const long long*)edges)[(long long)N_EDGES + e]
                    : ((const int*)edges)[N_EDGES + e];
    atomicAdd(&g_degi[d], 1);
}

// ---------------- k3: dinv + prefix scan (persistent, 148 blocks) ----------
__global__ __launch_bounds__(SCAN_THREADS)
void scan_kernel() {
    __shared__ int wsum[33];
    int tid = blockIdx.x * SCAN_THREADS + threadIdx.x;
    int v = 0;
    if (tid < N_NODES) {
        v = g_degi[tid];
        g_dinv[tid] = rsqrtf((float)v + 1.0f);
    }
    int lane = threadIdx.x & 31, w = threadIdx.x >> 5;
    int x = v;
#pragma unroll
    for (int off = 1; off < 32; off <<= 1) {
        int y = __shfl_up_sync(0xffffffffu, x, off);
        if (lane >= off) x += y;
    }
    if (lane == 31) wsum[w] = x;
    __syncthreads();
    if (w == 0) {
        int y = wsum[lane];
#pragma unroll
        for (int off = 1; off < 32; off <<= 1) {
            int z = __shfl_up_sync(0xffffffffu, y, off);
            if (lane >= off) y += z;
        }
        wsum[lane] = y;
    }
    __syncthreads();
    int incl_local = x + ((w > 0) ? wsum[w - 1] : 0);
    if (threadIdx.x == SCAN_THREADS - 1) g_bsum[blockIdx.x] = incl_local;
    grid_barrier(0);

    // cross-block prefix (warp 0 of each block sums preceding block totals)
    if (threadIdx.x < 32) {
        int acc = 0;
        for (int j = threadIdx.x; j < blockIdx.x; j += 32) acc += g_bsum[j];
#pragma unroll
        for (int off = 16; off > 0; off >>= 1)
            acc += __shfl_xor_sync(0xffffffffu, acc, off);
        if (threadIdx.x == 0) wsum[32] = acc;
    }
    __syncthreads();
    int incl = incl_local + wsum[32];
    if (tid < N_NODES) {
        g_off[tid] = incl - v;
        g_cur[tid] = incl - v;
        if (tid == N_NODES - 1) g_off[N_NODES] = incl;
    }
}

// ---------------- k4: CSR build (full grid, counting-sort scatter) ---------
__global__ void build_csr_kernel(const void* __restrict__ edges) {
    int e = blockIdx.x * blockDim.x + threadIdx.x;
    if (e >= N_EDGES) return;
    int s, d;
    if (g_idx64) {
        const long long* e64 = (const long long*)edges;
        s = (int)e64[e];
        d = (int)e64[(long long)N_EDGES + e];
    } else {
        const int* e32 = (const int*)edges;
        s = e32[e];
        d = e32[N_EDGES + e];
    }
    int pos = atomicAdd(&g_cur[d], 1);
    g_edge[pos] = make_int2(s, __float_as_int(g_dinv[s]));
}

// ------- GEMM1: h1 = X @ W1 (64 nodes/block, f32x2 packed FMA) ------------
__global__ __launch_bounds__(256) void gemm1_kernel(const float* __restrict__ X,
                                                    const float* __restrict__ W1) {
    __shared__ float2 xs2[64][65];   // self-duplicated x: (v,v), padded
    __shared__ float2 wst[32][65];   // wst[p][k] = (W1[k][2p], W1[k][2p+1]), padded
    int tid = threadIdx.x;
    int base = blockIdx.x * 64;

    for (int i = tid; i < 64 * 32; i += 256) {
        int k = i >> 5, p = i & 31;
        wst[p][k] = ((const float2*)W1)[i];  // i == k*32 + p
    }
    for (int i = tid; i < 64 * 64; i += 256) {
        int n = i >> 6, k = i & 63;
        int node = base + n;
        float v = (node < N_NODES) ? X[(size_t)node * 64 + k] : 0.0f;
        xs2[n][k] = make_float2(v, v);
    }
    __syncthreads();

    int node_t = tid >> 4;   // 0..15 -> 4 nodes each
    int col_t  = tid & 15;   // 0..15 -> col pairs col_t, col_t+16
    unsigned long long acc[4][2] = {};
#pragma unroll 8
    for (int k = 0; k < 64; k++) {
        unsigned long long xv[4], wv[2];
#pragma unroll
        for (int i = 0; i < 4; i++)
            xv[i] = *(const unsigned long long*)&xs2[node_t * 4 + i][k];
#pragma unroll
        for (int j = 0; j < 2; j++)
            wv[j] = *(const unsigned long long*)&wst[col_t + 16 * j][k];
#pragma unroll
        for (int i = 0; i < 4; i++)
#pragma unroll
            for (int j = 0; j < 2; j++)
                acc[i][j] = fma_f32x2(xv[i], wv[j], acc[i][j]);
    }
#pragma unroll
    for (int i = 0; i < 4; i++) {
        int node = base + node_t * 4 + i;
        if (node < N_NODES) {
            float2* out = (float2*)(g_h1 + (size_t)node * 64);
#pragma unroll
            for (int j = 0; j < 2; j++)
                out[col_t + 16 * j] = *(const float2*)&acc[i][j];
        }
    }
}

// ------- agg1 + gemm2 fused (shuffle-broadcast edge batches) --------------
__global__ __launch_bounds__(256) void agg1_gemm2_kernel(const float* __restrict__ b1,
                                                         const float* __restrict__ W2) {
    __shared__ float w2s[64][17];    // [k][c], padded
    __shared__ float x1s[8][64];     // per-warp x1 row
    int tid = threadIdx.x;
    for (int i = tid; i < 64 * 16; i += 256) w2s[i >> 4][i & 15] = W2[i];
    __syncthreads();

    int wy = tid >> 5;               // warp id 0..7
    int lane = tid & 31;
    int node = blockIdx.x * 8 + wy;
    if (node >= N_NODES) return;

    const float2* h1 = (const float2*)g_h1;
    float di = g_dinv[node];
    float2 acc = h1[(size_t)node * 32 + lane];
    acc.x *= di; acc.y *= di;        // self loop (final *di below)
    int beg = g_off[node], end = g_off[node + 1];

    for (int bb = beg; bb < end; bb += 32) {
        int2 e = make_int2(0, 0);
        if (bb + lane < end) e = g_edge[bb + lane];
        int cnt = min(end - bb, 32);
#pragma unroll 4
        for (int j = 0; j < cnt; j++) {
            int   s = __shfl_sync(0xffffffffu, e.x, j);
            float w = __int_as_float(__shfl_sync(0xffffffffu, e.y, j));
            float2 v = __ldg(&h1[(size_t)s * 32 + lane]);
            acc.x = fmaf(v.x, w, acc.x);
            acc.y = fmaf(v.y, w, acc.y);
        }
    }

    float rx = fmaxf(fmaf(acc.x, di, b1[2 * lane]), 0.0f);
    float ry = fmaxf(fmaf(acc.y, di, b1[2 * lane + 1]), 0.0f);
    x1s[wy][2 * lane]     = rx;
    x1s[wy][2 * lane + 1] = ry;
    __syncwarp();

    // in-warp gemm2: h2[c] = sum_k x1[k] * W2[k][c]
    int c = lane & 15, h = lane >> 4;
    float s = 0.0f;
#pragma unroll
    for (int kk = 0; kk < 32; kk++) {
        int k = h * 32 + kk;
        s = fmaf(x1s[wy][k], w2s[k][c], s);
    }
    s += __shfl_xor_sync(0xffffffffu, s, 16);
    if (h == 0) g_h2[(size_t)node * 16 + c] = s;
}

// ------- agg2: out = A_hat h2 + b2 (2 nodes/warp, independent halves) -----
__global__ __launch_bounds__(256) void agg2_kernel(const float* __restrict__ b2,
                                                   float* __restrict__ dout) {
    int wy = threadIdx.x >> 5;
    int lane = threadIdx.x & 31;
    int half = lane >> 4;            // 0 or 1 -> own node
    int c = lane & 15;               // column within h2 row
    unsigned mask = half ? 0xFFFF0000u : 0x0000FFFFu;
    int node = blockIdx.x * 16 + wy * 2 + half;
    if (node >= N_NODES) return;

    float di = g_dinv[node];
    float acc = g_h2[(size_t)node * 16 + c] * di;
    int beg = g_off[node], end = g_off[node + 1];

    for (int bb = beg; bb < end; bb += 16) {
        int2 e = make_int2(0, 0);
        if (bb + c < end) e = g_edge[bb + c];
        int cnt = min(end - bb, 16);
        for (int j = 0; j < cnt; j++) {
            int   s = __shfl_sync(mask, e.x, (half << 4) + j);
            float w = __int_as_float(__shfl_sync(mask, e.y, (half << 4) + j));
            acc = fmaf(__ldg(&g_h2[(size_t)s * 16 + c]), w, acc);
        }
    }
    dout[(size_t)node * 16 + c] = fmaf(acc, di, b2[c]);
}

// ---------------- launch --------------------------------------------------
extern "C" void kernel_launch(void* const* d_in, const int* in_sizes, int n_in,
                              void* d_out, int out_size) {
    const float* X  = (const float*)d_in[0];
    const void*  EI = (const void*)d_in[1];
    const float* W1 = (const float*)d_in[2];
    const float* b1 = (const float*)d_in[3];
    const float* W2 = (const float*)d_in[4];
    const float* b2 = (const float*)d_in[5];
    float* dout = (float*)d_out;
    (void)in_sizes; (void)n_in; (void)out_size;

    const int T = 256;
    zero_detect_kernel<<<(N_NODES + T - 1) / T, T>>>((const int*)EI);
    degree_kernel<<<(N_EDGES + T - 1) / T, T>>>(EI);
    scan_kernel<<<SCAN_BLOCKS, SCAN_THREADS>>>();
    build_csr_kernel<<<(N_EDGES + T - 1) / T, T>>>(EI);
    gemm1_kernel<<<(N_NODES + 63) / 64, 256>>>(X, W1);
    agg1_gemm2_kernel<<<(N_NODES + 7) / 8, 256>>>(b1, W2);
    agg2_kernel<<<(N_NODES + 15) / 16, 256>>>(b2, dout);
}

// round 10
// speedup vs baseline: 1.2693x; 1.0882x over previous
#include <cuda_runtime.h>
#include <cuda_bf16.h>

#define N_NODES 100000
#define N_EDGES 1000000
#define DF 64
#define NC 16
#define SCAN_BLOCKS 148
#define SCAN_THREADS 1024

// ---------------- device scratch (no allocations allowed) ----------------
__device__ int      g_degi[N_NODES];
__device__ float    g_dinv[N_NODES];
__device__ int      g_off[N_NODES + 1];
__device__ int      g_cur[N_NODES];
__device__ int      g_bsum[SCAN_BLOCKS];
__device__ int2     g_edge[N_EDGES];             // packed (src, bits(dinv[src]))
__device__ float    g_h1[(size_t)N_NODES * DF];  // X @ W1
__device__ float    g_h2[(size_t)N_NODES * NC];  // relu(agg1) @ W2
__device__ int      g_idx64;
__device__ unsigned g_barcnt[2];                 // cumulative grid-barrier tickets

// ---------------- cumulative grid barrier (graph-replay safe) -------------
__device__ __forceinline__ void grid_barrier(int i) {
    __syncthreads();
    if (threadIdx.x == 0) {
        __threadfence();
        unsigned tkt = atomicAdd(&g_barcnt[i], 1u) + 1u;
        unsigned target = ((tkt + (SCAN_BLOCKS - 1u)) / SCAN_BLOCKS) * SCAN_BLOCKS;
        volatile unsigned* p = &g_barcnt[i];
        while (*p < target) { }
        __threadfence();
    }
    __syncthreads();
}

// ---------------- packed f32x2 FMA ----------------------------------------
__device__ __forceinline__ unsigned long long fma_f32x2(unsigned long long a,
                                                        unsigned long long b,
                                                        unsigned long long c) {
    unsigned long long d;
    asm("fma.rn.f32x2 %0, %1, %2, %3;" : "=l"(d) : "l"(a), "l"(b), "l"(c));
    return d;
}

// ---------------- k1: zero degrees + detect index width --------------------
__global__ void zero_detect_kernel(const int* __restrict__ e32) {
    int i = blockIdx.x * blockDim.x + threadIdx.x;
    if (i < N_NODES) g_degi[i] = 0;
    if (blockIdx.x == 0) {
        __shared__ int any_nz;
        if (threadIdx.x == 0) any_nz = 0;
        __syncthreads();
        int nz = 0;
        for (int j = threadIdx.x; j < 4096; j += blockDim.x)
            if (e32[2 * j + 1] != 0) nz = 1;
        if (nz) any_nz = 1;
        __syncthreads();
        if (threadIdx.x == 0) g_idx64 = (any_nz == 0) ? 1 : 0;
    }
}

// ---------------- k2: in-degree histogram (full grid) ----------------------
__global__ void degree_kernel(const void* __restrict__ edges) {
    int e = blockIdx.x * blockDim.x + threadIdx.x;
    if (e >= N_EDGES) return;
    int d = g_idx64 ? (int)((const long long*)edges)[(long long)N_EDGES + e]
                    : ((const int*)edges)[N_EDGES + e];
    atomicAdd(&g_degi[d], 1);
}

// ---------------- k3: dinv + prefix scan (persistent, 148 blocks) ----------
__global__ __launch_bounds__(SCAN_THREADS)
void scan_kernel() {
    __shared__ int wsum[33];
    int tid = blockIdx.x * SCAN_THREADS + threadIdx.x;
    int v = 0;
    if (tid < N_NODES) {
        v = g_degi[tid];
        g_dinv[tid] = rsqrtf((float)v + 1.0f);
    }
    int lane = threadIdx.x & 31, w = threadIdx.x >> 5;
    int x = v;
#pragma unroll
    for (int off = 1; off < 32; off <<= 1) {
        int y = __shfl_up_sync(0xffffffffu, x, off);
        if (lane >= off) x += y;
    }
    if (lane == 31) wsum[w] = x;
    __syncthreads();
    if (w == 0) {
        int y = wsum[lane];
#pragma unroll
        for (int off = 1; off < 32; off <<= 1) {
            int z = __shfl_up_sync(0xffffffffu, y, off);
            if (lane >= off) y += z;
        }
        wsum[lane] = y;
    }
    __syncthreads();
    int incl_local = x + ((w > 0) ? wsum[w - 1] : 0);
    if (threadIdx.x == SCAN_THREADS - 1) g_bsum[blockIdx.x] = incl_local;
    grid_barrier(0);

    if (threadIdx.x < 32) {
        int acc = 0;
        for (int j = threadIdx.x; j < blockIdx.x; j += 32) acc += g_bsum[j];
#pragma unroll
        for (int off = 16; off > 0; off >>= 1)
            acc += __shfl_xor_sync(0xffffffffu, acc, off);
        if (threadIdx.x == 0) wsum[32] = acc;
    }
    __syncthreads();
    int incl = incl_local + wsum[32];
    if (tid < N_NODES) {
        g_off[tid] = incl - v;
        g_cur[tid] = incl - v;
        if (tid == N_NODES - 1) g_off[N_NODES] = incl;
    }
}

// ---------------- k4: CSR build (full grid, counting-sort scatter) ---------
__global__ void build_csr_kernel(const void* __restrict__ edges) {
    int e = blockIdx.x * blockDim.x + threadIdx.x;
    if (e >= N_EDGES) return;
    int s, d;
    if (g_idx64) {
        const long long* e64 = (const long long*)edges;
        s = (int)e64[e];
        d = (int)e64[(long long)N_EDGES + e];
    } else {
        const int* e32 = (const int*)edges;
        s = e32[e];
        d = e32[N_EDGES + e];
    }
    int pos = atomicAdd(&g_cur[d], 1);
    g_edge[pos] = make_int2(s, __float_as_int(g_dinv[s]));
}

// ------- GEMM1: h1 = X @ W1 (64 nodes/block, f32x2 packed FMA) ------------
__global__ __launch_bounds__(256) void gemm1_kernel(const float* __restrict__ X,
                                                    const float* __restrict__ W1) {
    __shared__ float2 xs2[64][65];   // self-duplicated x: (v,v), padded
    __shared__ float2 wst[32][65];   // wst[p][k] = (W1[k][2p], W1[k][2p+1]), padded
    int tid = threadIdx.x;
    int base = blockIdx.x * 64;

    for (int i = tid; i < 64 * 32; i += 256) {
        int k = i >> 5, p = i & 31;
        wst[p][k] = ((const float2*)W1)[i];  // i == k*32 + p
    }
    for (int i = tid; i < 64 * 64; i += 256) {
        int n = i >> 6, k = i & 63;
        int node = base + n;
        float v = (node < N_NODES) ? X[(size_t)node * 64 + k] : 0.0f;
        xs2[n][k] = make_float2(v, v);
    }
    __syncthreads();

    int node_t = tid >> 4;   // 0..15 -> 4 nodes each
    int col_t  = tid & 15;   // 0..15 -> col pairs col_t, col_t+16
    unsigned long long acc[4][2] = {};
#pragma unroll 8
    for (int k = 0; k < 64; k++) {
        unsigned long long xv[4], wv[2];
#pragma unroll
        for (int i = 0; i < 4; i++)
            xv[i] = *(const unsigned long long*)&xs2[node_t * 4 + i][k];
#pragma unroll
        for (int j = 0; j < 2; j++)
            wv[j] = *(const unsigned long long*)&wst[col_t + 16 * j][k];
#pragma unroll
        for (int i = 0; i < 4; i++)
#pragma unroll
            for (int j = 0; j < 2; j++)
                acc[i][j] = fma_f32x2(xv[i], wv[j], acc[i][j]);
    }
#pragma unroll
    for (int i = 0; i < 4; i++) {
        int node = base + node_t * 4 + i;
        if (node < N_NODES) {
            float2* out = (float2*)(g_h1 + (size_t)node * 64);
#pragma unroll
            for (int j = 0; j < 2; j++)
                out[col_t + 16 * j] = *(const float2*)&acc[i][j];
        }
    }
}

// ------- agg1 + gemm2 fused: 2 nodes/warp, float4 lanes, smem staging -----
__global__ __launch_bounds__(256) void agg1_gemm2_kernel(const float* __restrict__ b1,
                                                         const float* __restrict__ W2) {
    __shared__ float w2s[64][17];    // [k][c], padded
    __shared__ float x1s[16][65];    // per-node x1 row, padded
    __shared__ int2  est[8][2][16];  // per warp-half edge staging
    int tid = threadIdx.x;
    for (int i = tid; i < 64 * 16; i += 256) w2s[i >> 4][i & 15] = W2[i];
    __syncthreads();

    int wy   = tid >> 5;             // warp 0..7
    int lane = tid & 31;
    int half = lane >> 4;            // 0/1 -> own node
    int c    = lane & 15;            // 0..15 -> cols 4c..4c+3
    unsigned hmask = half ? 0xFFFF0000u : 0x0000FFFFu;
    int node = blockIdx.x * 16 + wy * 2 + half;
    bool active = (node < N_NODES);

    const float4* h1 = (const float4*)g_h1;
    float di = 0.0f;
    float4 acc = make_float4(0.f, 0.f, 0.f, 0.f);
    int beg = 0, end = 0;
    if (active) {
        di = g_dinv[node];
        acc = h1[(size_t)node * 16 + c];
        acc.x *= di; acc.y *= di; acc.z *= di; acc.w *= di;   // self loop
        beg = g_off[node]; end = g_off[node + 1];
    }

    for (int bb = beg; bb < end; bb += 16) {
        if (bb + c < end) est[wy][half][c] = g_edge[bb + c];
        __syncwarp(hmask);
        int cnt = min(end - bb, 16);
        for (int j = 0; j < cnt; j++) {
            int2 e = est[wy][half][j];           // LDS.64 broadcast
            float w = __int_as_float(e.y);
            float4 v = h1[(size_t)e.x * 16 + c]; // LDG.128
            acc.x = fmaf(v.x, w, acc.x);
            acc.y = fmaf(v.y, w, acc.y);
            acc.z = fmaf(v.z, w, acc.z);
            acc.w = fmaf(v.w, w, acc.w);
        }
        __syncwarp(hmask);
    }

    int nidx = wy * 2 + half;
    if (active) {
        float4 bb4 = ((const float4*)b1)[c];
        x1s[nidx][4 * c]     = fmaxf(fmaf(acc.x, di, bb4.x), 0.0f);
        x1s[nidx][4 * c + 1] = fmaxf(fmaf(acc.y, di, bb4.y), 0.0f);
        x1s[nidx][4 * c + 2] = fmaxf(fmaf(acc.z, di, bb4.z), 0.0f);
        x1s[nidx][4 * c + 3] = fmaxf(fmaf(acc.w, di, bb4.w), 0.0f);
    }
    __syncwarp(hmask);

    if (active) {
        float s = 0.0f;
#pragma unroll 8
        for (int k = 0; k < 64; k++)
            s = fmaf(x1s[nidx][k], w2s[k][c], s);
        g_h2[(size_t)node * 16 + c] = s;
    }
}

// ------- agg2: out = A_hat h2 + b2 (2 nodes/warp, smem staging) -----------
__global__ __launch_bounds__(256) void agg2_kernel(const float* __restrict__ b2,
                                                   float* __restrict__ dout) {
    __shared__ int2 est[8][2][16];
    int tid  = threadIdx.x;
    int wy   = tid >> 5;
    int lane = tid & 31;
    int half = lane >> 4;
    int c    = lane & 15;
    unsigned hmask = half ? 0xFFFF0000u : 0x0000FFFFu;
    int node = blockIdx.x * 16 + wy * 2 + half;
    if (node >= N_NODES) return;

    float di = g_dinv[node];
    float acc = g_h2[(size_t)node * 16 + c] * di;
    int beg = g_off[node], end = g_off[node + 1];

    for (int bb = beg; bb < end; bb += 16) {
        if (bb + c < end) est[wy][half][c] = g_edge[bb + c];
        __syncwarp(hmask);
        int cnt = min(end - bb, 16);
        for (int j = 0; j < cnt; j++) {
            int2 e = est[wy][half][j];           // LDS.64 broadcast
            float w = __int_as_float(e.y);
            acc = fmaf(__ldg(&g_h2[(size_t)e.x * 16 + c]), w, acc);
        }
        __syncwarp(hmask);
    }
    dout[(size_t)node * 16 + c] = fmaf(acc, di, b2[c]);
}

// ---------------- launch --------------------------------------------------
extern "C" void kernel_launch(void* const* d_in, const int* in_sizes, int n_in,
                              void* d_out, int out_size) {
    const float* X  = (const float*)d_in[0];
    const void*  EI = (const void*)d_in[1];
    const float* W1 = (const float*)d_in[2];
    const float* b1 = (const float*)d_in[3];
    const float* W2 = (const float*)d_in[4];
    const float* b2 = (const float*)d_in[5];
    float* dout = (float*)d_out;
    (void)in_sizes; (void)n_in; (void)out_size;

    const int T = 256;
    zero_detect_kernel<<<(N_NODES + T - 1) / T, T>>>((const int*)EI);
    degree_kernel<<<(N_EDGES + T - 1) / T, T>>>(EI);
    scan_kernel<<<SCAN_BLOCKS, SCAN_THREADS>>>();
    build_csr_kernel<<<(N_EDGES + T - 1) / T, T>>>(EI);
    gemm1_kernel<<<(N_NODES + 63) / 64, 256>>>(X, W1);
    agg1_gemm2_kernel<<<(N_NODES + 15) / 16, 256>>>(b1, W2);
    agg2_kernel<<<(N_NODES + 15) / 16, 256>>>(b2, dout);
}